// round 9
// baseline (speedup 1.0000x reference)
#include <cuda_runtime.h>
#include <math.h>
#include <stdint.h>

#define B_  2
#define S_  4096
#define D_  768
#define H_  12
#define HD_ 64
#define M_  (B_ * S_)   // 8192

// Scratch (allocation-free rule: __device__ globals)
__device__ float gQ[(size_t)B_ * H_ * S_ * HD_];   // [B,H,S,HD], scaled by log2e/8
__device__ float gK[(size_t)B_ * H_ * S_ * HD_];
__device__ float gV[(size_t)B_ * H_ * S_ * HD_];
__device__ float gCtx[(size_t)B_ * S_ * D_];

// ---------------------------------------------------------------------------
__device__ __forceinline__ uint32_t to_tf32(float v) {
    uint32_t t;
    asm("cvt.rna.tf32.f32 %0, %1;" : "=r"(t) : "f"(v));
    return t;
}
__device__ __forceinline__ float ex2f(float x) {
    float y;
    asm("ex2.approx.ftz.f32 %0, %1;" : "=f"(y) : "f"(x));
    return y;
}
// D += A * B  (m16n8k8, tf32, row.col)
__device__ __forceinline__ void mma_tf32(float* d, const uint32_t* a, const uint32_t* b) {
    asm volatile(
        "mma.sync.aligned.m16n8k8.row.col.f32.tf32.tf32.f32 "
        "{%0,%1,%2,%3}, {%4,%5,%6,%7}, {%8,%9}, {%0,%1,%2,%3};\n"
        : "+f"(d[0]), "+f"(d[1]), "+f"(d[2]), "+f"(d[3])
        : "r"(a[0]), "r"(a[1]), "r"(a[2]), "r"(a[3]), "r"(b[0]), "r"(b[1]));
}

// ---------------------------------------------------------------------------
// tf32 GEMM (unchanged from R4): out = (X @ W^T + bias) * scale.
// ---------------------------------------------------------------------------
#define XSTR 36
__global__ void __launch_bounds__(256) gemm_tf32_kernel(
    const float* __restrict__ X, const float* __restrict__ W,
    const float* __restrict__ bias, float* __restrict__ out,
    float scale, int scatter)
{
    __shared__ float sX[128 * XSTR];
    __shared__ float sW[64 * XSTR];

    const int tid  = threadIdx.x;
    const int l    = tid & 31;
    const int wid  = tid >> 5;
    const int wm   = wid >> 1;
    const int wn   = wid & 1;
    const int r0   = l >> 2;
    const int c0   = l & 3;
    const int m0   = blockIdx.y << 7;
    const int n0   = blockIdx.x << 6;

    const int xr = tid >> 1, xc = (tid & 1) << 4;
    const float* xp = X + (size_t)(m0 + xr) * D_ + xc;
    const float* wp = W + (size_t)(n0 + (tid >> 1)) * D_ + ((tid & 1) << 4);

    float4 rx[4], rw[4];
#pragma unroll
    for (int u = 0; u < 4; u++) rx[u] = *(const float4*)(xp + 4 * u);
    if (tid < 128) {
#pragma unroll
        for (int u = 0; u < 4; u++) rw[u] = *(const float4*)(wp + 4 * u);
    }

    float acc[2][4][4] = {};

    for (int kt = 0; kt < D_ / 32; kt++) {
        {
            float* dx = &sX[xr * XSTR + xc];
#pragma unroll
            for (int u = 0; u < 4; u++) {
                float4 f;
                f.x = __uint_as_float(to_tf32(rx[u].x));
                f.y = __uint_as_float(to_tf32(rx[u].y));
                f.z = __uint_as_float(to_tf32(rx[u].z));
                f.w = __uint_as_float(to_tf32(rx[u].w));
                *(float4*)(dx + 4 * u) = f;
            }
            if (tid < 128) {
                float* dw = &sW[(tid >> 1) * XSTR + ((tid & 1) << 4)];
#pragma unroll
                for (int u = 0; u < 4; u++) {
                    float4 f;
                    f.x = __uint_as_float(to_tf32(rw[u].x));
                    f.y = __uint_as_float(to_tf32(rw[u].y));
                    f.z = __uint_as_float(to_tf32(rw[u].z));
                    f.w = __uint_as_float(to_tf32(rw[u].w));
                    *(float4*)(dw + 4 * u) = f;
                }
            }
        }
        __syncthreads();

        if (kt + 1 < D_ / 32) {
            const int ko = (kt + 1) * 32;
#pragma unroll
            for (int u = 0; u < 4; u++) rx[u] = *(const float4*)(xp + ko + 4 * u);
            if (tid < 128) {
#pragma unroll
                for (int u = 0; u < 4; u++) rw[u] = *(const float4*)(wp + ko + 4 * u);
            }
        }

#pragma unroll
        for (int ks = 0; ks < 4; ks++) {
            const int kk = ks * 8 + c0;
            uint32_t a[2][4], b[4][2];
#pragma unroll
            for (int i = 0; i < 2; i++) {
                const float* ab = &sX[(wm * 32 + i * 16 + r0) * XSTR];
                a[i][0] = __float_as_uint(ab[kk]);
                a[i][1] = __float_as_uint(ab[8 * XSTR + kk]);
                a[i][2] = __float_as_uint(ab[kk + 4]);
                a[i][3] = __float_as_uint(ab[8 * XSTR + kk + 4]);
            }
#pragma unroll
            for (int j = 0; j < 4; j++) {
                const float* bb = &sW[(wn * 32 + j * 8 + r0) * XSTR];
                b[j][0] = __float_as_uint(bb[kk]);
                b[j][1] = __float_as_uint(bb[kk + 4]);
            }
#pragma unroll
            for (int i = 0; i < 2; i++)
#pragma unroll
                for (int j = 0; j < 4; j++)
                    mma_tf32(acc[i][j], a[i], b[j]);
        }
        __syncthreads();
    }

    const int qr = l >> 2;
    const int qc = (l & 3) << 1;
#pragma unroll
    for (int j = 0; j < 4; j++) {
        const int n = n0 + (wn << 5) + (j << 3) + qc;
        const float b0 = bias[n], b1 = bias[n + 1];
#pragma unroll
        for (int i = 0; i < 2; i++) {
#pragma unroll
            for (int h = 0; h < 2; h++) {
                const int m = m0 + (wm << 5) + (i << 4) + qr + (h << 3);
                float2 v;
                v.x = (acc[i][j][h * 2 + 0] + b0) * scale;
                v.y = (acc[i][j][h * 2 + 1] + b1) * scale;
                if (scatter) {
                    const int bb = m >> 12, ss = m & 4095;
                    const int hh = n >> 6, hd = n & 63;
                    *(float2*)&out[(((size_t)(bb * H_ + hh) * S_ + ss) << 6) + hd] = v;
                } else {
                    *(float2*)&out[(size_t)m * D_ + n] = v;
                }
            }
        }
    }
}

// ---------------------------------------------------------------------------
// Flash attention v3 (fixed): CTA = 128q x 64kv, 128 threads, 4 warps x 32q.
// kv-chunk-fused: per 8-kv chunk do QK -> no-max softmax -> shuffle P -> PV.
// lsum is per-lane partial (2 cols/chunk); quad-reduced ONCE at the end
// (this was the R6 NaN bug: missing reduction -> lsum=0 on fully-masked
// lanes of the qt=0 diagonal CTA -> inf * 0 = NaN).
// ---------------------------------------------------------------------------
#define KSTR 68
#define VSTR 72

__global__ void __launch_bounds__(128) attn_kernel(
    const float* __restrict__ Qg, const float* __restrict__ Kg,
    const float* __restrict__ Vg, float* __restrict__ ctx)
{
    __shared__ float sK[64 * KSTR];
    __shared__ float sV[64 * VSTR];

    const int tid = threadIdx.x;
    const int l   = tid & 31;
    const int w   = tid >> 5;
    const int r0  = l >> 2;
    const int c0  = l & 3;
    const int bh  = blockIdx.y;
    const int qt  = (int)(gridDim.x - 1) - (int)blockIdx.x;  // longest first
    const int q0  = qt * 128;
    const int wq  = w * 32;

    const float* Qp = Qg + ((size_t)bh * S_ + q0 + wq) * HD_;
    const float* Kp = Kg + (size_t)bh * S_ * HD_;
    const float* Vp = Vg + (size_t)bh * S_ * HD_;

    // Q A-frags in registers: 2 groups of 16 rows
    uint32_t qf[2][8][4];
#pragma unroll
    for (int g = 0; g < 2; g++) {
        const float* qg_ = Qp + (size_t)(g * 16) * HD_;
#pragma unroll
        for (int ks = 0; ks < 8; ks++) {
            const int hd = ks * 8 + c0;
            qf[g][ks][0] = to_tf32(qg_[(size_t)r0 * HD_ + hd]);
            qf[g][ks][1] = to_tf32(qg_[(size_t)(r0 + 8) * HD_ + hd]);
            qf[g][ks][2] = to_tf32(qg_[(size_t)r0 * HD_ + hd + 4]);
            qf[g][ks][3] = to_tf32(qg_[(size_t)(r0 + 8) * HD_ + hd + 4]);
        }
    }

    float o[2][8][4] = {};
    float lsum[2][2] = {};

    const int ldr = tid >> 1;            // 0..63
    const int ldc = (tid & 1) << 5;      // 0,32

    // shuffle constants for P C-frag -> A-frag
    const int sl0 = (l & ~3) | (c0 >> 1);
    const int sl2 = sl0 + 2;
    const bool hp = (c0 & 1) != 0;

    const int ntiles = 2 * qt + 2;
    for (int t = 0; t < ntiles; t++) {
        // --- stage K/V tile -> tf32 -> padded raw smem ---
        {
            const float* kg = Kp + ((size_t)(t * 64 + ldr)) * HD_ + ldc;
            const float* vg = Vp + ((size_t)(t * 64 + ldr)) * HD_ + ldc;
            float* kd = &sK[ldr * KSTR + ldc];
            float* vd = &sV[ldr * VSTR + ldc];
#pragma unroll
            for (int i = 0; i < 8; i++) {
                const float4 f = *(const float4*)(kg + 4 * i);
                const float4 g = *(const float4*)(vg + 4 * i);
                float4 fc, gc;
                fc.x = __uint_as_float(to_tf32(f.x));
                fc.y = __uint_as_float(to_tf32(f.y));
                fc.z = __uint_as_float(to_tf32(f.z));
                fc.w = __uint_as_float(to_tf32(f.w));
                gc.x = __uint_as_float(to_tf32(g.x));
                gc.y = __uint_as_float(to_tf32(g.y));
                gc.z = __uint_as_float(to_tf32(g.z));
                gc.w = __uint_as_float(to_tf32(g.w));
                *(float4*)(kd + 4 * i) = fc;
                *(float4*)(vd + 4 * i) = gc;
            }
        }
        __syncthreads();

        const bool need_mask = (t >= 2 * qt);

        // --- per 8-kv chunk: QK -> softmax -> PV ---
#pragma unroll
        for (int nt = 0; nt < 8; nt++) {
            // QK for this chunk: s[g] = Q_g x K_chunk^T
            float s[2][4] = {};
#pragma unroll
            for (int ks = 0; ks < 8; ks++) {
                const int kk = ks * 8 + c0;
                const float* kb = &sK[(nt * 8 + r0) * KSTR];
                uint32_t b[2];
                b[0] = __float_as_uint(kb[kk]);
                b[1] = __float_as_uint(kb[kk + 4]);
                mma_tf32(s[0], qf[0][ks], b);
                mma_tf32(s[1], qf[1][ks], b);
            }

            // no-max softmax piece: p = exp2(s), masked -> 0, tf32-rounded
            float p[2][4];
#pragma unroll
            for (int g = 0; g < 2; g++) {
                float p0 = ex2f(s[g][0]);
                float p1 = ex2f(s[g][1]);
                float p2 = ex2f(s[g][2]);
                float p3 = ex2f(s[g][3]);
                if (need_mask) {
                    const int kvb = t * 64 + nt * 8 + 2 * c0;
                    const int qlo = q0 + wq + g * 16 + r0;
                    const int qhi = qlo + 8;
                    if (kvb     > qlo) p0 = 0.0f;
                    if (kvb + 1 > qlo) p1 = 0.0f;
                    if (kvb     > qhi) p2 = 0.0f;
                    if (kvb + 1 > qhi) p3 = 0.0f;
                }
                p0 = __uint_as_float(to_tf32(p0));
                p1 = __uint_as_float(to_tf32(p1));
                p2 = __uint_as_float(to_tf32(p2));
                p3 = __uint_as_float(to_tf32(p3));
                lsum[g][0] += p0 + p1;
                lsum[g][1] += p2 + p3;
                p[g][0] = p0; p[g][1] = p1; p[g][2] = p2; p[g][3] = p3;
            }

            // P C-frag -> A-frag via shuffles (per group)
            uint32_t a[2][4];
#pragma unroll
            for (int g = 0; g < 2; g++) {
                const float v0a = __shfl_sync(0xffffffffu, p[g][0], sl0);
                const float v0b = __shfl_sync(0xffffffffu, p[g][1], sl0);
                const float v1a = __shfl_sync(0xffffffffu, p[g][2], sl0);
                const float v1b = __shfl_sync(0xffffffffu, p[g][3], sl0);
                const float v2a = __shfl_sync(0xffffffffu, p[g][0], sl2);
                const float v2b = __shfl_sync(0xffffffffu, p[g][1], sl2);
                const float v3a = __shfl_sync(0xffffffffu, p[g][2], sl2);
                const float v3b = __shfl_sync(0xffffffffu, p[g][3], sl2);
                a[g][0] = __float_as_uint(hp ? v0b : v0a);
                a[g][1] = __float_as_uint(hp ? v1b : v1a);
                a[g][2] = __float_as_uint(hp ? v2b : v2a);
                a[g][3] = __float_as_uint(hp ? v3b : v3a);
            }

            // PV for this chunk: O_g += P_chunk x V_chunk
            const float* vb0 = &sV[(nt * 8 + c0) * VSTR];
            const float* vb1 = &sV[(nt * 8 + c0 + 4) * VSTR];
#pragma unroll
            for (int ntv = 0; ntv < 8; ntv++) {
                uint32_t b[2];
                b[0] = __float_as_uint(vb0[ntv * 8 + r0]);
                b[1] = __float_as_uint(vb1[ntv * 8 + r0]);
                mma_tf32(o[0][ntv], a[0], b);
                mma_tf32(o[1][ntv], a[1], b);
            }
        }
        __syncthreads();
    }

    // --- quad-reduce row sums (R6 fix), normalize + write ctx [B,S,D] ---
    {
#pragma unroll
        for (int g = 0; g < 2; g++) {
#pragma unroll
            for (int hh = 0; hh < 2; hh++) {
                lsum[g][hh] += __shfl_xor_sync(0xffffffffu, lsum[g][hh], 1);
                lsum[g][hh] += __shfl_xor_sync(0xffffffffu, lsum[g][hh], 2);
            }
        }

        const int b_ = bh / H_;
        const int h_ = bh % H_;
#pragma unroll
        for (int g = 0; g < 2; g++) {
            const float inv0 = 1.0f / lsum[g][0];
            const float inv1 = 1.0f / lsum[g][1];
            const size_t base0 = ((size_t)b_ * S_ + q0 + wq + g * 16 + r0) * D_ + h_ * HD_;
            const size_t base1 = base0 + (size_t)8 * D_;
#pragma unroll
            for (int ntv = 0; ntv < 8; ntv++) {
                float2 w0, w1;
                w0.x = o[g][ntv][0] * inv0; w0.y = o[g][ntv][1] * inv0;
                w1.x = o[g][ntv][2] * inv1; w1.y = o[g][ntv][3] * inv1;
                *(float2*)&ctx[base0 + ntv * 8 + 2 * c0] = w0;
                *(float2*)&ctx[base1 + ntv * 8 + 2 * c0] = w1;
            }
        }
    }
}

// ---------------------------------------------------------------------------
extern "C" void kernel_launch(void* const* d_in, const int* in_sizes, int n_in,
                              void* d_out, int out_size)
{
    const float* x  = (const float*)d_in[0];
    const float* Wq = (const float*)d_in[1];
    const float* bq = (const float*)d_in[2];
    const float* Wk = (const float*)d_in[3];
    const float* bk = (const float*)d_in[4];
    const float* Wv = (const float*)d_in[5];
    const float* bv = (const float*)d_in[6];
    const float* Wo = (const float*)d_in[7];
    const float* bo = (const float*)d_in[8];
    float* out = (float*)d_out;

    float *q, *k, *v, *c;
    cudaGetSymbolAddress((void**)&q, gQ);
    cudaGetSymbolAddress((void**)&k, gK);
    cudaGetSymbolAddress((void**)&v, gV);
    cudaGetSymbolAddress((void**)&c, gCtx);

    const dim3 gblk(D_ / 64, M_ / 128);   // (12, 64)
    // fold 1/sqrt(64) * log2(e) into Q so softmax uses ex2
    gemm_tf32_kernel<<<gblk, 256>>>(x, Wq, bq, q, 0.125f * 1.4426950408889634f, 1);
    gemm_tf32_kernel<<<gblk, 256>>>(x, Wk, bk, k, 1.0f, 1);
    gemm_tf32_kernel<<<gblk, 256>>>(x, Wv, bv, v, 1.0f, 1);

    attn_kernel<<<dim3(S_ / 128, B_ * H_), 128>>>(q, k, v, c);

    gemm_tf32_kernel<<<gblk, 256>>>(c, Wo, bo, out, 1.0f, 0);
}